// round 5
// baseline (speedup 1.0000x reference)
#include <cuda_runtime.h>
#include <cuda_bf16.h>
#include <math.h>
#include <stdint.h>

// Problem constants
#define B_ 2
#define L_ 2048
#define D_ 2048
#define H_ 8
#define HD_ 256
#define FD_ 64
#define FEAT_ 128          // 2*FD
#define CHUNK_ 64
#define NCH_ (L_/CHUNK_)   // 32
#define HALF_ (HD_/2)      // 128

// ---------------- scratch (device globals; no allocation allowed) ----------
__device__ float g_q [B_*L_*H_*HD_];
__device__ float g_k [B_*L_*HD_];
__device__ float g_v [B_*L_*HD_];
__device__ float g_qf[B_*H_*L_*FEAT_];
__device__ float g_kf[B_*H_*L_*FEAT_];
__device__ float g_kv[B_*H_*NCH_*FEAT_*HD_];
__device__ float g_o [B_*L_*H_*HD_];

// bf16 split operands
__device__ __nv_bfloat16 g_hh[B_*L_*D_], g_hl[B_*L_*D_];          // hidden hi/lo
__device__ __nv_bfloat16 g_oh[B_*L_*H_*HD_], g_ol[B_*L_*H_*HD_];  // o hi/lo
__device__ __nv_bfloat16 g_wqh[D_*H_*HD_], g_wql[D_*H_*HD_];      // WqT [N,K]
__device__ __nv_bfloat16 g_wkh[HD_*D_],    g_wkl[HD_*D_];         // WkT
__device__ __nv_bfloat16 g_wvh[HD_*D_],    g_wvl[HD_*D_];         // WvT
__device__ __nv_bfloat16 g_woh[D_*H_*HD_], g_wol[D_*H_*HD_];      // WoT

// ---------------- helpers ---------------------------------------------------
__device__ __forceinline__ uint32_t packbf(float lo, float hi) {
    uint32_t r;
    asm("cvt.rn.bf16x2.f32 %0, %1, %2;" : "=r"(r) : "f"(hi), "f"(lo));
    return r;
}
__device__ __forceinline__ uint32_t residbf(uint32_t p, float x0, float x1) {
    float h0 = __uint_as_float(p << 16);
    float h1 = __uint_as_float(p & 0xFFFF0000u);
    return packbf(x0 - h0, x1 - h1);
}
__device__ __forceinline__ void mma_bf16(float* d,
                                         const uint32_t* a,
                                         const uint32_t* b) {
    asm volatile(
        "mma.sync.aligned.m16n8k16.row.col.f32.bf16.bf16.f32 "
        "{%0,%1,%2,%3}, {%4,%5,%6,%7}, {%8,%9}, {%0,%1,%2,%3};\n"
        : "+f"(d[0]), "+f"(d[1]), "+f"(d[2]), "+f"(d[3])
        : "r"(a[0]), "r"(a[1]), "r"(a[2]), "r"(a[3]),
          "r"(b[0]), "r"(b[1]));
}
__device__ __forceinline__ void cp16(void* smem_dst, const void* gmem_src) {
    uint32_t s = (uint32_t)__cvta_generic_to_shared(smem_dst);
    asm volatile("cp.async.ca.shared.global [%0], [%1], 16;\n"
                 :: "r"(s), "l"(gmem_src));
}
__device__ __forceinline__ void cp_commit() {
    asm volatile("cp.async.commit_group;\n");
}

// ---------------- split kernels --------------------------------------------
__global__ __launch_bounds__(256)
void split_kernel(const float* __restrict__ x,
                  __nv_bfloat16* __restrict__ hi,
                  __nv_bfloat16* __restrict__ lo, int n) {
    int i = (blockIdx.x*256 + threadIdx.x) * 4;
    if (i >= n) return;
    float4 v = *(const float4*)(x + i);
    uint32_t h0 = packbf(v.x, v.y);
    uint32_t h1 = packbf(v.z, v.w);
    uint32_t l0 = residbf(h0, v.x, v.y);
    uint32_t l1 = residbf(h1, v.z, v.w);
    *(uint2*)(hi + i) = make_uint2(h0, h1);
    *(uint2*)(lo + i) = make_uint2(l0, l1);
}

// W [K,N] fp32 -> WT hi/lo [N,K] bf16 (z batches two matrices)
__global__ __launch_bounds__(256)
void splitT_kernel(const float* __restrict__ W0, __nv_bfloat16* th0, __nv_bfloat16* tl0,
                   const float* __restrict__ W1, __nv_bfloat16* th1, __nv_bfloat16* tl1,
                   int K, int N) {
    const float* W = blockIdx.z ? W1 : W0;
    __nv_bfloat16* th = blockIdx.z ? th1 : th0;
    __nv_bfloat16* tl = blockIdx.z ? tl1 : tl0;
    __shared__ float tile[32][33];
    int n0 = blockIdx.x*32, k0 = blockIdx.y*32;
    int tx = threadIdx.x & 31, ty = threadIdx.x >> 5;  // 32x8
    #pragma unroll
    for (int r = 0; r < 32; r += 8)
        tile[ty + r][tx] = W[(size_t)(k0 + ty + r)*N + n0 + tx];
    __syncthreads();
    #pragma unroll
    for (int r = 0; r < 32; r += 8) {
        float v = tile[tx][ty + r];
        __nv_bfloat16 h = __float2bfloat16(v);
        __nv_bfloat16 l = __float2bfloat16(v - __bfloat162float(h));
        size_t oi = (size_t)(n0 + ty + r)*K + k0 + tx;
        th[oi] = h; tl[oi] = l;
    }
}

// ============================================================================
// Pre-split BF16 GEMM: C[M,N] = A[M,K] * B[K,N], A as (Ah+Al)[M,K] bf16,
// B as transposed splits (BTh+BTl)[N,K] bf16. 3-term: AhBh + AhBl + AlBh.
// Tile 128x128x16, 8 warps (2x4), warp 64x32, mma m16n8k16. No cvts in loop.
// ============================================================================
#define LDW 12   // u32 row stride (8 data words + 4 pad): conflict-free frags

__global__ __launch_bounds__(256, 2)
void bfgemm2_kernel(int M, int N, int K,
                    const __nv_bfloat16* __restrict__ Ah,
                    const __nv_bfloat16* __restrict__ Al,
                    const __nv_bfloat16* __restrict__ Bh0,
                    const __nv_bfloat16* __restrict__ Bl0, float* __restrict__ C0,
                    const __nv_bfloat16* __restrict__ Bh1,
                    const __nv_bfloat16* __restrict__ Bl1, float* __restrict__ C1) {
    __shared__ uint32_t sA[2][2][128][LDW];   // [stage][hi/lo][row][words]
    __shared__ uint32_t sB[2][2][128][LDW];

    const __nv_bfloat16* Bh = blockIdx.z ? Bh1 : Bh0;
    const __nv_bfloat16* Bl = blockIdx.z ? Bl1 : Bl0;
    float* C = blockIdx.z ? C1 : C0;

    const int tid = threadIdx.x, lane = tid & 31, warp = tid >> 5;
    const int warpM = warp & 1, warpN = warp >> 1;
    const int g = lane >> 2, t4 = lane & 3;
    const int cRow = blockIdx.y, cCol = blockIdx.x;

    const int row = tid >> 1, half = tid & 1;        // copy mapping
    const __nv_bfloat16* aH = Ah + (size_t)(cRow*128 + row)*K + half*8;
    const __nv_bfloat16* aL = Al + (size_t)(cRow*128 + row)*K + half*8;
    const __nv_bfloat16* bH = Bh + (size_t)(cCol*128 + row)*K + half*8;
    const __nv_bfloat16* bL = Bl + (size_t)(cCol*128 + row)*K + half*8;

    float acc[4][4][4];
    #pragma unroll
    for (int mt = 0; mt < 4; mt++)
        #pragma unroll
        for (int nt = 0; nt < 4; nt++)
            #pragma unroll
            for (int i = 0; i < 4; i++) acc[mt][nt][i] = 0.f;

    const int KT = K >> 4;

    // prologue
    cp16(&sA[0][0][row][half*4], aH);
    cp16(&sA[0][1][row][half*4], aL);
    cp16(&sB[0][0][row][half*4], bH);
    cp16(&sB[0][1][row][half*4], bL);
    cp_commit();

    for (int kt = 0; kt < KT; kt++) {
        if (kt + 1 < KT) {
            const int s = (kt + 1) & 1;
            const int ko = (kt + 1) * 16;
            cp16(&sA[s][0][row][half*4], aH + ko);
            cp16(&sA[s][1][row][half*4], aL + ko);
            cp16(&sB[s][0][row][half*4], bH + ko);
            cp16(&sB[s][1][row][half*4], bL + ko);
            cp_commit();
            asm volatile("cp.async.wait_group 1;\n");
        } else {
            asm volatile("cp.async.wait_group 0;\n");
        }
        __syncthreads();

        const int s = kt & 1;

        uint32_t bhf[4][2], blf[4][2];
        #pragma unroll
        for (int nt = 0; nt < 4; nt++) {
            const int n0 = warpN*32 + nt*8 + g;
            bhf[nt][0] = sB[s][0][n0][t4];
            bhf[nt][1] = sB[s][0][n0][t4 + 4];
            blf[nt][0] = sB[s][1][n0][t4];
            blf[nt][1] = sB[s][1][n0][t4 + 4];
        }
        #pragma unroll
        for (int mt = 0; mt < 4; mt++) {
            const int r0 = warpM*64 + mt*16 + g;
            uint32_t ahf[4], alf[4];
            ahf[0] = sA[s][0][r0][t4];     ahf[1] = sA[s][0][r0 + 8][t4];
            ahf[2] = sA[s][0][r0][t4 + 4]; ahf[3] = sA[s][0][r0 + 8][t4 + 4];
            alf[0] = sA[s][1][r0][t4];     alf[1] = sA[s][1][r0 + 8][t4];
            alf[2] = sA[s][1][r0][t4 + 4]; alf[3] = sA[s][1][r0 + 8][t4 + 4];
            #pragma unroll
            for (int nt = 0; nt < 4; nt++) {
                mma_bf16(acc[mt][nt], ahf, bhf[nt]);
                mma_bf16(acc[mt][nt], ahf, blf[nt]);
                mma_bf16(acc[mt][nt], alf, bhf[nt]);
            }
        }
        __syncthreads();
    }

    // epilogue
    float* Cb = C + (size_t)cRow*128*N + cCol*128;
    #pragma unroll
    for (int mt = 0; mt < 4; mt++) {
        const int r0 = warpM*64 + mt*16 + g;
        #pragma unroll
        for (int nt = 0; nt < 4; nt++) {
            const int c = warpN*32 + nt*8 + t4*2;
            *(float2*)&Cb[(size_t)r0 * N + c]       = make_float2(acc[mt][nt][0], acc[mt][nt][1]);
            *(float2*)&Cb[(size_t)(r0 + 8) * N + c] = make_float2(acc[mt][nt][2], acc[mt][nt][3]);
        }
    }
}

// ---------------- RoPE (in place) -----------------------------------------
__global__ void rope_kernel(float* __restrict__ x,
                            const float* __restrict__ cs,
                            const float* __restrict__ sn,
                            int heads) {
    int idx = blockIdx.x*blockDim.x + threadIdx.x;
    int total = B_*L_*heads*HALF_;
    if (idx >= total) return;
    int j = idx % HALF_;
    int h = (idx / HALF_) % heads;
    int l = (idx / (HALF_*heads)) % L_;
    int b =  idx / (HALF_*heads*L_);
    float c = cs[l*HALF_ + j];
    float s = sn[l*HALF_ + j];
    float* row = x + ((size_t)(b*L_ + l)*heads + h)*HD_;
    float x1 = row[j], x2 = row[j + HALF_];
    row[j]        = x1*c - x2*s;
    row[j + HALF_] = x1*s + x2*c;
}

// ---------------- Hedgehog feature map ------------------------------------
__global__ __launch_bounds__(256)
void hedgehog_kernel(const float* __restrict__ x,
                     const float* __restrict__ fm,
                     float* __restrict__ outf,
                     int xh, float scale) {
    __shared__ float xs[16][HD_];
    __shared__ float ps[16][FD_];
    __shared__ float ms[16], zs[16];

    int h = blockIdx.y, b = blockIdx.z;
    int l0 = blockIdx.x * 16;
    int t = threadIdx.x;
    int srcH = (xh == 1) ? 0 : h;

    for (int e = t; e < 16*HD_; e += 256) {
        int r = e / HD_, d = e % HD_;
        xs[r][d] = x[((size_t)(b*L_ + l0 + r)*xh + srcH)*HD_ + d];
    }
    __syncthreads();

    int r  = t / 16;
    int fb = (t % 16) * 4;
    float a0=0.f, a1=0.f, a2=0.f, a3=0.f;
    const float* fmh = fm + (size_t)h*HD_*FD_;
    #pragma unroll 4
    for (int d = 0; d < HD_; d++) {
        float xv = xs[r][d];
        float4 w = *(const float4*)&fmh[d*FD_ + fb];
        a0 += xv*w.x; a1 += xv*w.y; a2 += xv*w.z; a3 += xv*w.w;
    }
    ps[r][fb+0]=a0; ps[r][fb+1]=a1; ps[r][fb+2]=a2; ps[r][fb+3]=a3;
    __syncthreads();

    if (t < 16) {
        float m = 0.f;
        for (int f = 0; f < FD_; f++) m = fmaxf(m, fabsf(ps[t][f]));
        float z = 0.f;
        for (int f = 0; f < FD_; f++)
            z += __expf(ps[t][f] - m) + __expf(-ps[t][f] - m);
        ms[t] = m; zs[t] = z;
    }
    __syncthreads();

    for (int e = t; e < 16*FEAT_; e += 256) {
        int rr = e / FEAT_, f = e % FEAT_;
        float p = (f < FD_) ? ps[rr][f] : -ps[rr][f - FD_];
        float val = __expf(p - ms[rr]) / zs[rr] * scale;
        outf[((size_t)(b*H_ + h)*L_ + l0 + rr)*FEAT_ + f] = val;
    }
}

// ---------------- per-chunk kv state (register-tiled) ----------------------
// kv[f,d] = sum_c kf[c,f] * v[c,d]; block = 128f x 128d tile of one chunk.
__global__ __launch_bounds__(256)
void kv2_kernel(const float* __restrict__ kf, const float* __restrict__ v,
                float* __restrict__ kv) {
    __shared__ float ks[32][FEAT_];   // 16 KB
    __shared__ float vs[32][128];     // 16 KB
    int n  = blockIdx.x;
    int dh = blockIdx.y;              // 0..1 (128-wide d half)
    int bh = blockIdx.z;
    int b  = bh / H_;
    int t  = threadIdx.x;
    int tf = t >> 4;                  // 0..15  -> f0 = tf*8
    int td = t & 15;                  // 0..15  -> d = td*4 and 64+td*4

    const float* kfp = kf + ((size_t)bh*L_ + n*CHUNK_)*FEAT_;
    const float* vp  = v  + ((size_t)b*L_  + n*CHUNK_)*HD_ + dh*128;

    float acc[8][8];
    #pragma unroll
    for (int i = 0; i < 8; i++)
        #pragma unroll
        for (int j = 0; j < 8; j++) acc[i][j] = 0.f;

    for (int cc = 0; cc < 2; cc++) {
        for (int e = t; e < 32*FEAT_; e += 256)
            ks[e >> 7][e & 127] = kfp[cc*32*FEAT_ + e];
        for (int e = t; e < 32*128; e += 256) {
            int r = e >> 7, c = e & 127;
            vs[r][c] = vp[(size_t)(cc*32 + r)*HD_ + c];
        }
        __syncthreads();

        #pragma unroll 4
        for (int c = 0; c < 32; c++) {
            float4 ka = *(const float4*)&ks[c][tf*8];
            float4 kb = *(const float4*)&ks[c][tf*8 + 4];
            float4 va = *(const float4*)&vs[c][td*4];
            float4 vb = *(const float4*)&vs[c][64 + td*4];
            float kk[8] = {ka.x,ka.y,ka.z,ka.w,kb.x,kb.y,kb.z,kb.w};
            float vv[8] = {va.x,va.y,va.z,va.w,vb.x,vb.y,vb.z,vb.w};
            #pragma unroll
            for (int i = 0; i < 8; i++)
                #pragma unroll
                for (int j = 0; j < 8; j++)
                    acc[i][j] += kk[i]*vv[j];
        }
        __syncthreads();
    }

    float* out = kv + ((size_t)(bh*NCH_ + n)*FEAT_)*HD_ + dh*128;
    #pragma unroll
    for (int i = 0; i < 8; i++) {
        size_t ro = (size_t)(tf*8 + i)*HD_;
        *(float4*)&out[ro + td*4]      = make_float4(acc[i][0], acc[i][1], acc[i][2], acc[i][3]);
        *(float4*)&out[ro + 64 + td*4] = make_float4(acc[i][4], acc[i][5], acc[i][6], acc[i][7]);
    }
}

// ---------------- exclusive cumsum over chunk axis (in place) -------------
__global__ void cumsum_kernel(float* __restrict__ kv) {
    int bh = blockIdx.y;
    int e  = blockIdx.x*256 + threadIdx.x;
    float* base = kv + (size_t)bh*NCH_*FEAT_*HD_ + e;
    float run = 0.f;
    for (int n = 0; n < NCH_; n++) {
        float tmp = base[(size_t)n*FEAT_*HD_];
        base[(size_t)n*FEAT_*HD_] = run;
        run += tmp;
    }
}

// ---------------- inter + intra chunk attention ---------------------------
__global__ __launch_bounds__(256)
void attn_kernel(const float* __restrict__ qf, const float* __restrict__ kf,
                 const float* __restrict__ v,  const float* __restrict__ kv,
                 float* __restrict__ o) {
    __shared__ float qs[CHUNK_][FEAT_];
    __shared__ float ss[CHUNK_][CHUNK_];
    int n = blockIdx.x, h = blockIdx.y, b = blockIdx.z;
    int bh = b*H_ + h;
    int t = threadIdx.x;
    int j = t;

    const float* qp = qf + ((size_t)bh*L_ + n*CHUNK_)*FEAT_;
    for (int e = t; e < CHUNK_*FEAT_; e += 256) qs[e/FEAT_][e%FEAT_] = qp[e];
    __syncthreads();

    float acc[CHUNK_];
    #pragma unroll
    for (int i = 0; i < CHUNK_; i++) acc[i] = 0.f;

    const float* kvp = kv + ((size_t)(bh*NCH_ + n)*FEAT_)*HD_;
    for (int f = 0; f < FEAT_; f += 4) {
        float k0 = kvp[(size_t)(f+0)*HD_ + j];
        float k1 = kvp[(size_t)(f+1)*HD_ + j];
        float k2 = kvp[(size_t)(f+2)*HD_ + j];
        float k3 = kvp[(size_t)(f+3)*HD_ + j];
        #pragma unroll
        for (int i = 0; i < CHUNK_; i++) {
            float4 qv = *(const float4*)&qs[i][f];
            acc[i] += qv.x*k0 + qv.y*k1 + qv.z*k2 + qv.w*k3;
        }
    }

    {
        const float* kp = kf + ((size_t)bh*L_ + n*CHUNK_)*FEAT_;
        int i   = t / 4;
        int jp0 = (t % 4) * 16;
        for (int jj = 0; jj < 16; jj++) {
            int jp = jp0 + jj;
            float sum = 0.f;
            if (jp <= i) {
                const float* krow = kp + (size_t)jp*FEAT_;
                #pragma unroll 8
                for (int f = 0; f < FEAT_; f += 4) {
                    float4 qv = *(const float4*)&qs[i][f];
                    float4 kr = *(const float4*)&krow[f];
                    sum += qv.x*kr.x + qv.y*kr.y + qv.z*kr.z + qv.w*kr.w;
                }
            }
            ss[i][jp] = sum;
        }
    }
    __syncthreads();

    const float* vp = v + ((size_t)b*L_ + n*CHUNK_)*HD_;
    for (int jp = 0; jp < CHUNK_; jp += 4) {
        float v0 = vp[(size_t)(jp+0)*HD_ + j];
        float v1 = vp[(size_t)(jp+1)*HD_ + j];
        float v2 = vp[(size_t)(jp+2)*HD_ + j];
        float v3 = vp[(size_t)(jp+3)*HD_ + j];
        #pragma unroll
        for (int i = 0; i < CHUNK_; i++) {
            float4 sv = *(const float4*)&ss[i][jp];
            acc[i] += sv.x*v0 + sv.y*v1 + sv.z*v2 + sv.w*v3;
        }
    }

    float* op = o + ((size_t)(b*L_ + n*CHUNK_))*(H_*HD_) + h*HD_ + j;
    #pragma unroll
    for (int i = 0; i < CHUNK_; i++) op[(size_t)i*(H_*HD_)] = acc[i];
}

// ---------------- launch ---------------------------------------------------
// Q-projection GEMM placed at launch index 3 (the ncu-captured slot).
extern "C" void kernel_launch(void* const* d_in, const int* in_sizes, int n_in,
                              void* d_out, int out_size) {
    const float* hidden = (const float*)d_in[0];
    const float* fcos   = (const float*)d_in[1];
    const float* fsin   = (const float*)d_in[2];
    // d_in[3] = mask (unused)
    const float* Wq     = (const float*)d_in[4];
    const float* Wk     = (const float*)d_in[5];
    const float* Wv     = (const float*)d_in[6];
    const float* Wo     = (const float*)d_in[7];
    const float* fmq    = (const float*)d_in[8];
    const float* fmk    = (const float*)d_in[9];
    float* out          = (float*)d_out;

    float *q, *k, *v, *qf, *kf, *kv, *o;
    cudaGetSymbolAddress((void**)&q,  g_q);
    cudaGetSymbolAddress((void**)&k,  g_k);
    cudaGetSymbolAddress((void**)&v,  g_v);
    cudaGetSymbolAddress((void**)&qf, g_qf);
    cudaGetSymbolAddress((void**)&kf, g_kf);
    cudaGetSymbolAddress((void**)&kv, g_kv);
    cudaGetSymbolAddress((void**)&o,  g_o);

    __nv_bfloat16 *hh,*hl,*oh,*ol,*wqh,*wql,*wkh,*wkl,*wvh,*wvl,*woh,*wol;
    cudaGetSymbolAddress((void**)&hh,  g_hh);  cudaGetSymbolAddress((void**)&hl,  g_hl);
    cudaGetSymbolAddress((void**)&oh,  g_oh);  cudaGetSymbolAddress((void**)&ol,  g_ol);
    cudaGetSymbolAddress((void**)&wqh, g_wqh); cudaGetSymbolAddress((void**)&wql, g_wql);
    cudaGetSymbolAddress((void**)&wkh, g_wkh); cudaGetSymbolAddress((void**)&wkl, g_wkl);
    cudaGetSymbolAddress((void**)&wvh, g_wvh); cudaGetSymbolAddress((void**)&wvl, g_wvl);
    cudaGetSymbolAddress((void**)&woh, g_woh); cudaGetSymbolAddress((void**)&wol, g_wol);

    const int M = B_*L_;   // 4096
    const float qscale = 0.08838834764831845f;   // 128^-0.5

    // 0: split hidden -> bf16 hi/lo
    split_kernel<<<(M*D_)/1024, 256>>>(hidden, hh, hl, M*D_);
    // 1: split+transpose Wq  [D, 2048] -> [2048, D]
    splitT_kernel<<<dim3((H_*HD_)/32, D_/32, 1), 256>>>(Wq, wqh, wql, Wq, wqh, wql, D_, H_*HD_);
    // 2: split+transpose Wk, Wv  [D, 256] -> [256, D]
    splitT_kernel<<<dim3(HD_/32, D_/32, 2), 256>>>(Wk, wkh, wkl, Wv, wvh, wvl, D_, HD_);
    // 3: Q projection  (profiled slot)
    bfgemm2_kernel<<<dim3((H_*HD_)/128, M/128, 1), 256>>>(M, H_*HD_, D_,
        hh, hl, wqh, wql, q, wqh, wql, q);
    // 4: split+transpose Wo  [2048, D] -> [D, 2048]
    splitT_kernel<<<dim3(D_/32, (H_*HD_)/32, 1), 256>>>(Wo, woh, wol, Wo, woh, wol, H_*HD_, D_);
    // 5: K and V projections (z-batched)
    bfgemm2_kernel<<<dim3(HD_/128, M/128, 2), 256>>>(M, HD_, D_,
        hh, hl, wkh, wkl, k, wvh, wvl, v);
    // 6,7: RoPE
    rope_kernel<<<(B_*L_*HALF_ + 255)/256, 256>>>(k, fcos, fsin, 1);
    rope_kernel<<<(B_*L_*H_*HALF_ + 255)/256, 256>>>(q, fcos, fsin, H_);
    // 8,9: hedgehog
    hedgehog_kernel<<<dim3(L_/16, H_, B_), 256>>>(k, fmk, kf, 1, 1.0f);
    hedgehog_kernel<<<dim3(L_/16, H_, B_), 256>>>(q, fmq, qf, H_, qscale);
    // 10: per-chunk kv states
    kv2_kernel<<<dim3(NCH_, 2, B_*H_), 256>>>(kf, v, kv);
    // 11: exclusive cumsum
    cumsum_kernel<<<dim3(128, B_*H_), 256>>>(kv);
    // 12: inter + intra attention
    attn_kernel<<<dim3(NCH_, H_, B_), 256>>>(qf, kf, v, kv, o);
    // 13: split o
    split_kernel<<<(M*H_*HD_)/1024, 256>>>(o, oh, ol, M*H_*HD_);
    // 14: output projection
    bfgemm2_kernel<<<dim3(D_/128, M/128, 1), 256>>>(M, D_, H_*HD_,
        oh, ol, woh, wol, out, woh, wol, out);
}

// round 6
// speedup vs baseline: 1.1445x; 1.1445x over previous
#include <cuda_runtime.h>
#include <cuda_bf16.h>
#include <math.h>
#include <stdint.h>

// Problem constants
#define B_ 2
#define L_ 2048
#define D_ 2048
#define H_ 8
#define HD_ 256
#define FD_ 64
#define FEAT_ 128          // 2*FD
#define CHUNK_ 64
#define NCH_ (L_/CHUNK_)   // 32
#define HALF_ (HD_/2)      // 128

// ---------------- scratch (device globals; no allocation allowed) ----------
__device__ float g_q [B_*L_*H_*HD_];
__device__ float g_k [B_*L_*HD_];
__device__ float g_v [B_*L_*HD_];
__device__ float g_qf[B_*H_*L_*FEAT_];
__device__ float g_kf[B_*H_*L_*FEAT_];
__device__ float g_kv[B_*H_*NCH_*FEAT_*HD_];
__device__ float g_o [B_*L_*H_*HD_];

__device__ __nv_bfloat16 g_hh[B_*L_*D_], g_hl[B_*L_*D_];
__device__ __nv_bfloat16 g_oh[B_*L_*H_*HD_], g_ol[B_*L_*H_*HD_];
__device__ __nv_bfloat16 g_wqh[D_*H_*HD_], g_wql[D_*H_*HD_];
__device__ __nv_bfloat16 g_wkh[HD_*D_],    g_wkl[HD_*D_];
__device__ __nv_bfloat16 g_wvh[HD_*D_],    g_wvl[HD_*D_];
__device__ __nv_bfloat16 g_woh[D_*H_*HD_], g_wol[D_*H_*HD_];

// ---------------- helpers ---------------------------------------------------
__device__ __forceinline__ uint32_t packbf(float lo, float hi) {
    uint32_t r;
    asm("cvt.rn.bf16x2.f32 %0, %1, %2;" : "=r"(r) : "f"(hi), "f"(lo));
    return r;
}
__device__ __forceinline__ uint32_t residbf(uint32_t p, float x0, float x1) {
    float h0 = __uint_as_float(p << 16);
    float h1 = __uint_as_float(p & 0xFFFF0000u);
    return packbf(x0 - h0, x1 - h1);
}
__device__ __forceinline__ void mma_bf16(float* d,
                                         const uint32_t* a,
                                         const uint32_t* b) {
    asm volatile(
        "mma.sync.aligned.m16n8k16.row.col.f32.bf16.bf16.f32 "
        "{%0,%1,%2,%3}, {%4,%5,%6,%7}, {%8,%9}, {%0,%1,%2,%3};\n"
        : "+f"(d[0]), "+f"(d[1]), "+f"(d[2]), "+f"(d[3])
        : "r"(a[0]), "r"(a[1]), "r"(a[2]), "r"(a[3]),
          "r"(b[0]), "r"(b[1]));
}
__device__ __forceinline__ void cp16s(uint32_t saddr, const void* g) {
    asm volatile("cp.async.ca.shared.global [%0], [%1], 16;\n"
                 :: "r"(saddr), "l"(g));
}
__device__ __forceinline__ void cp_commit() {
    asm volatile("cp.async.commit_group;\n");
}
__device__ __forceinline__ void ldsm4(uint32_t* r, uint32_t saddr) {
    asm volatile("ldmatrix.sync.aligned.m8n8.x4.shared.b16 {%0,%1,%2,%3}, [%4];\n"
                 : "=r"(r[0]), "=r"(r[1]), "=r"(r[2]), "=r"(r[3]) : "r"(saddr));
}

// ---------------- split kernels --------------------------------------------
__global__ __launch_bounds__(256)
void split_kernel(const float* __restrict__ x,
                  __nv_bfloat16* __restrict__ hi,
                  __nv_bfloat16* __restrict__ lo, int n) {
    int i = (blockIdx.x*256 + threadIdx.x) * 4;
    if (i >= n) return;
    float4 v = *(const float4*)(x + i);
    uint32_t h0 = packbf(v.x, v.y);
    uint32_t h1 = packbf(v.z, v.w);
    uint32_t l0 = residbf(h0, v.x, v.y);
    uint32_t l1 = residbf(h1, v.z, v.w);
    *(uint2*)(hi + i) = make_uint2(h0, h1);
    *(uint2*)(lo + i) = make_uint2(l0, l1);
}

__global__ __launch_bounds__(256)
void splitT_kernel(const float* __restrict__ W0, __nv_bfloat16* th0, __nv_bfloat16* tl0,
                   const float* __restrict__ W1, __nv_bfloat16* th1, __nv_bfloat16* tl1,
                   int K, int N) {
    const float* W = blockIdx.z ? W1 : W0;
    __nv_bfloat16* th = blockIdx.z ? th1 : th0;
    __nv_bfloat16* tl = blockIdx.z ? tl1 : tl0;
    __shared__ float tile[32][33];
    int n0 = blockIdx.x*32, k0 = blockIdx.y*32;
    int tx = threadIdx.x & 31, ty = threadIdx.x >> 5;
    #pragma unroll
    for (int r = 0; r < 32; r += 8)
        tile[ty + r][tx] = W[(size_t)(k0 + ty + r)*N + n0 + tx];
    __syncthreads();
    #pragma unroll
    for (int r = 0; r < 32; r += 8) {
        float v = tile[tx][ty + r];
        __nv_bfloat16 h = __float2bfloat16(v);
        __nv_bfloat16 l = __float2bfloat16(v - __bfloat162float(h));
        size_t oi = (size_t)(n0 + ty + r)*K + k0 + tx;
        th[oi] = h; tl[oi] = l;
    }
}

// ============================================================================
// bfgemm3: 3-stage cp.async pipeline + ldmatrix frags + fused multi-output.
// A (M,K) pre-split bf16 hi/lo; B transposed [N,K] pre-split bf16 hi/lo.
// Block tile 128x128x16; 8 warps (2x4); warp 64x32; mma m16n8k16.
// grid.x columns: [0,nq) -> Q output, [nq,nq+nk) -> K output, rest -> V.
// Dynamic smem: 3 stages x (Ahi,Alo,Bhi,Blo) x 128 rows x 12 words = 72 KB.
// ============================================================================
#define LDWW 12            // words per row (8 data + 4 pad)
#define SECW (128*LDWW)    // 1536 words per section
#define STW  (4*SECW)      // 6144 words per stage
#define SMEM_BYTES (3*STW*4)

__global__ __launch_bounds__(256, 2)
void bfgemm3_kernel(int M, int K, int nq, int nk,
                    const __nv_bfloat16* __restrict__ Ah,
                    const __nv_bfloat16* __restrict__ Al,
                    const __nv_bfloat16* __restrict__ qBh, const __nv_bfloat16* __restrict__ qBl,
                    float* __restrict__ qC, int qN,
                    const __nv_bfloat16* __restrict__ kBh, const __nv_bfloat16* __restrict__ kBl,
                    float* __restrict__ kC,
                    const __nv_bfloat16* __restrict__ vBh, const __nv_bfloat16* __restrict__ vBl,
                    float* __restrict__ vC) {
    extern __shared__ uint32_t smem[];
    const uint32_t smem_u32 = (uint32_t)__cvta_generic_to_shared(smem);

    // per-block output selection
    const int cx = blockIdx.x;
    const __nv_bfloat16 *Bh, *Bl;
    float* C;
    int N, ccol;
    if (cx < nq)            { Bh = qBh; Bl = qBl; C = qC; N = qN;  ccol = cx; }
    else if (cx < nq + nk)  { Bh = kBh; Bl = kBl; C = kC; N = 256; ccol = cx - nq; }
    else                    { Bh = vBh; Bl = vBl; C = vC; N = 256; ccol = cx - nq - nk; }

    const int tid = threadIdx.x, lane = tid & 31, warp = tid >> 5;
    const int warpM = warp & 1, warpN = warp >> 1;
    const int cRow = blockIdx.y;

    // copy mapping: each thread 1x16B per section
    const int row = tid >> 1, half = tid & 1;
    const __nv_bfloat16* aH = Ah + (size_t)(cRow*128 + row)*K + half*8;
    const __nv_bfloat16* aL = Al + (size_t)(cRow*128 + row)*K + half*8;
    const __nv_bfloat16* bH = Bh + (size_t)(ccol*128 + row)*K + half*8;
    const __nv_bfloat16* bL = Bl + (size_t)(ccol*128 + row)*K + half*8;
    const uint32_t dstw = row*LDWW + half*4;   // word offset within section

    // ldmatrix per-lane offsets (words)
    const int l7 = lane & 7;
    const uint32_t aoffw = (uint32_t)((warpM*64 + l7 + ((lane>>3)&1)*8)*LDWW + (lane>>4)*4);
    uint32_t boffw[2];
    #pragma unroll
    for (int p = 0; p < 2; p++)
        boffw[p] = (uint32_t)((warpN*32 + p*16 + l7 + ((lane>>4)&1)*8)*LDWW + ((lane>>3)&1)*4);

    float acc[4][4][4];
    #pragma unroll
    for (int mt = 0; mt < 4; mt++)
        #pragma unroll
        for (int nt = 0; nt < 4; nt++)
            #pragma unroll
            for (int i = 0; i < 4; i++) acc[mt][nt][i] = 0.f;

    const int KT = K >> 4;   // 128

    // prologue: stages 0 and 1
    #pragma unroll
    for (int s = 0; s < 2; s++) {
        const int ko = s*16;
        const uint32_t sb = smem_u32 + (s*STW)*4;
        cp16s(sb + (0*SECW + dstw)*4, aH + ko);
        cp16s(sb + (1*SECW + dstw)*4, aL + ko);
        cp16s(sb + (2*SECW + dstw)*4, bH + ko);
        cp16s(sb + (3*SECW + dstw)*4, bL + ko);
        cp_commit();
    }

    int sc = 0;  // compute stage index (mod 3)
    for (int kt = 0; kt < KT; kt++) {
        if (kt < KT - 1) { asm volatile("cp.async.wait_group 1;\n"); }
        else             { asm volatile("cp.async.wait_group 0;\n"); }
        __syncthreads();

        // prefetch stage kt+2 into buffer (kt+2)%3 (computed at kt-1; safe post-sync)
        if (kt + 2 < KT) {
            const int sl = (sc + 2 >= 3) ? sc - 1 : sc + 2;
            const int ko = (kt + 2)*16;
            const uint32_t sb = smem_u32 + (sl*STW)*4;
            cp16s(sb + (0*SECW + dstw)*4, aH + ko);
            cp16s(sb + (1*SECW + dstw)*4, aL + ko);
            cp16s(sb + (2*SECW + dstw)*4, bH + ko);
            cp16s(sb + (3*SECW + dstw)*4, bL + ko);
            cp_commit();
        }

        const uint32_t sb = smem_u32 + (sc*STW)*4;

        // B fragments: 4 ldmatrix.x4
        uint32_t bhf[2][4], blf[2][4];
        #pragma unroll
        for (int p = 0; p < 2; p++) {
            ldsm4(bhf[p], sb + (2*SECW + boffw[p])*4);
            ldsm4(blf[p], sb + (3*SECW + boffw[p])*4);
        }

        // A fragments per mt + 12 MMAs
        #pragma unroll
        for (int mt = 0; mt < 4; mt++) {
            uint32_t ahf[4], alf[4];
            const uint32_t ao = aoffw + mt*16*LDWW;
            ldsm4(ahf, sb + (0*SECW + ao)*4);
            ldsm4(alf, sb + (1*SECW + ao)*4);
            #pragma unroll
            for (int nt = 0; nt < 4; nt++) {
                const uint32_t* bp = &bhf[nt >> 1][(nt & 1)*2];
                const uint32_t* lp = &blf[nt >> 1][(nt & 1)*2];
                mma_bf16(acc[mt][nt], ahf, bp);
                mma_bf16(acc[mt][nt], ahf, lp);
                mma_bf16(acc[mt][nt], alf, bp);
            }
        }
        sc = (sc + 1 == 3) ? 0 : sc + 1;
    }

    // epilogue
    const int g = lane >> 2, t4 = lane & 3;
    float* Cb = C + (size_t)cRow*128*N + ccol*128;
    #pragma unroll
    for (int mt = 0; mt < 4; mt++) {
        const int r0 = warpM*64 + mt*16 + g;
        #pragma unroll
        for (int nt = 0; nt < 4; nt++) {
            const int c = warpN*32 + nt*8 + t4*2;
            *(float2*)&Cb[(size_t)r0 * N + c]       = make_float2(acc[mt][nt][0], acc[mt][nt][1]);
            *(float2*)&Cb[(size_t)(r0 + 8) * N + c] = make_float2(acc[mt][nt][2], acc[mt][nt][3]);
        }
    }
}

// ---------------- RoPE (in place) -----------------------------------------
__global__ void rope_kernel(float* __restrict__ x,
                            const float* __restrict__ cs,
                            const float* __restrict__ sn,
                            int heads) {
    int idx = blockIdx.x*blockDim.x + threadIdx.x;
    int total = B_*L_*heads*HALF_;
    if (idx >= total) return;
    int j = idx % HALF_;
    int h = (idx / HALF_) % heads;
    int l = (idx / (HALF_*heads)) % L_;
    int b =  idx / (HALF_*heads*L_);
    float c = cs[l*HALF_ + j];
    float s = sn[l*HALF_ + j];
    float* row = x + ((size_t)(b*L_ + l)*heads + h)*HD_;
    float x1 = row[j], x2 = row[j + HALF_];
    row[j]        = x1*c - x2*s;
    row[j + HALF_] = x1*s + x2*c;
}

// ---------------- Hedgehog feature map ------------------------------------
__global__ __launch_bounds__(256)
void hedgehog_kernel(const float* __restrict__ x,
                     const float* __restrict__ fm,
                     float* __restrict__ outf,
                     int xh, float scale) {
    __shared__ float xs[16][HD_];
    __shared__ float ps[16][FD_];
    __shared__ float ms[16], zs[16];

    int h = blockIdx.y, b = blockIdx.z;
    int l0 = blockIdx.x * 16;
    int t = threadIdx.x;
    int srcH = (xh == 1) ? 0 : h;

    for (int e = t; e < 16*HD_; e += 256) {
        int r = e / HD_, d = e % HD_;
        xs[r][d] = x[((size_t)(b*L_ + l0 + r)*xh + srcH)*HD_ + d];
    }
    __syncthreads();

    int r  = t / 16;
    int fb = (t % 16) * 4;
    float a0=0.f, a1=0.f, a2=0.f, a3=0.f;
    const float* fmh = fm + (size_t)h*HD_*FD_;
    #pragma unroll 4
    for (int d = 0; d < HD_; d++) {
        float xv = xs[r][d];
        float4 w = *(const float4*)&fmh[d*FD_ + fb];
        a0 += xv*w.x; a1 += xv*w.y; a2 += xv*w.z; a3 += xv*w.w;
    }
    ps[r][fb+0]=a0; ps[r][fb+1]=a1; ps[r][fb+2]=a2; ps[r][fb+3]=a3;
    __syncthreads();

    if (t < 16) {
        float m = 0.f;
        for (int f = 0; f < FD_; f++) m = fmaxf(m, fabsf(ps[t][f]));
        float z = 0.f;
        for (int f = 0; f < FD_; f++)
            z += __expf(ps[t][f] - m) + __expf(-ps[t][f] - m);
        ms[t] = m; zs[t] = z;
    }
    __syncthreads();

    for (int e = t; e < 16*FEAT_; e += 256) {
        int rr = e / FEAT_, f = e % FEAT_;
        float p = (f < FD_) ? ps[rr][f] : -ps[rr][f - FD_];
        float val = __expf(p - ms[rr]) / zs[rr] * scale;
        outf[((size_t)(b*H_ + h)*L_ + l0 + rr)*FEAT_ + f] = val;
    }
}

// ---------------- per-chunk kv state (register-tiled) ----------------------
__global__ __launch_bounds__(256)
void kv2_kernel(const float* __restrict__ kf, const float* __restrict__ v,
                float* __restrict__ kv) {
    __shared__ float ks[32][FEAT_];
    __shared__ float vs[32][128];
    int n  = blockIdx.x;
    int dh = blockIdx.y;
    int bh = blockIdx.z;
    int b  = bh / H_;
    int t  = threadIdx.x;
    int tf = t >> 4;
    int td = t & 15;

    const float* kfp = kf + ((size_t)bh*L_ + n*CHUNK_)*FEAT_;
    const float* vp  = v  + ((size_t)b*L_  + n*CHUNK_)*HD_ + dh*128;

    float acc[8][8];
    #pragma unroll
    for (int i = 0; i < 8; i++)
        #pragma unroll
        for (int j = 0; j < 8; j++) acc[i][j] = 0.f;

    for (int cc = 0; cc < 2; cc++) {
        for (int e = t; e < 32*FEAT_; e += 256)
            ks[e >> 7][e & 127] = kfp[cc*32*FEAT_ + e];
        for (int e = t; e < 32*128; e += 256) {
            int r = e >> 7, c = e & 127;
            vs[r][c] = vp[(size_t)(cc*32 + r)*HD_ + c];
        }
        __syncthreads();

        #pragma unroll 4
        for (int c = 0; c < 32; c++) {
            float4 ka = *(const float4*)&ks[c][tf*8];
            float4 kb = *(const float4*)&ks[c][tf*8 + 4];
            float4 va = *(const float4*)&vs[c][td*4];
            float4 vb = *(const float4*)&vs[c][64 + td*4];
            float kk[8] = {ka.x,ka.y,ka.z,ka.w,kb.x,kb.y,kb.z,kb.w};
            float vv[8] = {va.x,va.y,va.z,va.w,vb.x,vb.y,vb.z,vb.w};
            #pragma unroll
            for (int i = 0; i < 8; i++)
                #pragma unroll
                for (int j = 0; j < 8; j++)
                    acc[i][j] += kk[i]*vv[j];
        }
        __syncthreads();
    }

    float* out = kv + ((size_t)(bh*NCH_ + n)*FEAT_)*HD_ + dh*128;
    #pragma unroll
    for (int i = 0; i < 8; i++) {
        size_t ro = (size_t)(tf*8 + i)*HD_;
        *(float4*)&out[ro + td*4]      = make_float4(acc[i][0], acc[i][1], acc[i][2], acc[i][3]);
        *(float4*)&out[ro + 64 + td*4] = make_float4(acc[i][4], acc[i][5], acc[i][6], acc[i][7]);
    }
}

// ---------------- exclusive cumsum over chunk axis (in place) -------------
__global__ void cumsum_kernel(float* __restrict__ kv) {
    int bh = blockIdx.y;
    int e  = blockIdx.x*256 + threadIdx.x;
    float* base = kv + (size_t)bh*NCH_*FEAT_*HD_ + e;
    float run = 0.f;
    for (int n = 0; n < NCH_; n++) {
        float tmp = base[(size_t)n*FEAT_*HD_];
        base[(size_t)n*FEAT_*HD_] = run;
        run += tmp;
    }
}

// ---------------- inter + intra chunk attention ---------------------------
__global__ __launch_bounds__(256)
void attn_kernel(const float* __restrict__ qf, const float* __restrict__ kf,
                 const float* __restrict__ v,  const float* __restrict__ kv,
                 float* __restrict__ o) {
    __shared__ float qs[CHUNK_][FEAT_];
    __shared__ float ss[CHUNK_][CHUNK_];
    int n = blockIdx.x, h = blockIdx.y, b = blockIdx.z;
    int bh = b*H_ + h;
    int t = threadIdx.x;
    int j = t;

    const float* qp = qf + ((size_t)bh*L_ + n*CHUNK_)*FEAT_;
    for (int e = t; e < CHUNK_*FEAT_; e += 256) qs[e/FEAT_][e%FEAT_] = qp[e];
    __syncthreads();

    float acc[CHUNK_];
    #pragma unroll
    for (int i = 0; i < CHUNK_; i++) acc[i] = 0.f;

    const float* kvp = kv + ((size_t)(bh*NCH_ + n)*FEAT_)*HD_;
    for (int f = 0; f < FEAT_; f += 4) {
        float k0 = kvp[(size_t)(f+0)*HD_ + j];
        float k1 = kvp[(size_t)(f+1)*HD_ + j];
        float k2 = kvp[(size_t)(f+2)*HD_ + j];
        float k3 = kvp[(size_t)(f+3)*HD_ + j];
        #pragma unroll
        for (int i = 0; i < CHUNK_; i++) {
            float4 qv = *(const float4*)&qs[i][f];
            acc[i] += qv.x*k0 + qv.y*k1 + qv.z*k2 + qv.w*k3;
        }
    }

    {
        const float* kp = kf + ((size_t)bh*L_ + n*CHUNK_)*FEAT_;
        int i   = t / 4;
        int jp0 = (t % 4) * 16;
        for (int jj = 0; jj < 16; jj++) {
            int jp = jp0 + jj;
            float sum = 0.f;
            if (jp <= i) {
                const float* krow = kp + (size_t)jp*FEAT_;
                #pragma unroll 8
                for (int f = 0; f < FEAT_; f += 4) {
                    float4 qv = *(const float4*)&qs[i][f];
                    float4 kr = *(const float4*)&krow[f];
                    sum += qv.x*kr.x + qv.y*kr.y + qv.z*kr.z + qv.w*kr.w;
                }
            }
            ss[i][jp] = sum;
        }
    }
    __syncthreads();

    const float* vp = v + ((size_t)b*L_ + n*CHUNK_)*HD_;
    for (int jp = 0; jp < CHUNK_; jp += 4) {
        float v0 = vp[(size_t)(jp+0)*HD_ + j];
        float v1 = vp[(size_t)(jp+1)*HD_ + j];
        float v2 = vp[(size_t)(jp+2)*HD_ + j];
        float v3 = vp[(size_t)(jp+3)*HD_ + j];
        #pragma unroll
        for (int i = 0; i < CHUNK_; i++) {
            float4 sv = *(const float4*)&ss[i][jp];
            acc[i] += sv.x*v0 + sv.y*v1 + sv.z*v2 + sv.w*v3;
        }
    }

    float* op = o + ((size_t)(b*L_ + n*CHUNK_))*(H_*HD_) + h*HD_ + j;
    #pragma unroll
    for (int i = 0; i < CHUNK_; i++) op[(size_t)i*(H_*HD_)] = acc[i];
}

// ---------------- launch ---------------------------------------------------
extern "C" void kernel_launch(void* const* d_in, const int* in_sizes, int n_in,
                              void* d_out, int out_size) {
    const float* hidden = (const float*)d_in[0];
    const float* fcos   = (const float*)d_in[1];
    const float* fsin   = (const float*)d_in[2];
    // d_in[3] = mask (unused)
    const float* Wq     = (const float*)d_in[4];
    const float* Wk     = (const float*)d_in[5];
    const float* Wv     = (const float*)d_in[6];
    const float* Wo     = (const float*)d_in[7];
    const float* fmq    = (const float*)d_in[8];
    const float* fmk    = (const float*)d_in[9];
    float* out          = (float*)d_out;

    float *q, *k, *v, *qf, *kf, *kv, *o;
    cudaGetSymbolAddress((void**)&q,  g_q);
    cudaGetSymbolAddress((void**)&k,  g_k);
    cudaGetSymbolAddress((void**)&v,  g_v);
    cudaGetSymbolAddress((void**)&qf, g_qf);
    cudaGetSymbolAddress((void**)&kf, g_kf);
    cudaGetSymbolAddress((void**)&kv, g_kv);
    cudaGetSymbolAddress((void**)&o,  g_o);

    __nv_bfloat16 *hh,*hl,*oh,*ol,*wqh,*wql,*wkh,*wkl,*wvh,*wvl,*woh,*wol;
    cudaGetSymbolAddress((void**)&hh,  g_hh);  cudaGetSymbolAddress((void**)&hl,  g_hl);
    cudaGetSymbolAddress((void**)&oh,  g_oh);  cudaGetSymbolAddress((void**)&ol,  g_ol);
    cudaGetSymbolAddress((void**)&wqh, g_wqh); cudaGetSymbolAddress((void**)&wql, g_wql);
    cudaGetSymbolAddress((void**)&wkh, g_wkh); cudaGetSymbolAddress((void**)&wkl, g_wkl);
    cudaGetSymbolAddress((void**)&wvh, g_wvh); cudaGetSymbolAddress((void**)&wvl, g_wvl);
    cudaGetSymbolAddress((void**)&woh, g_woh); cudaGetSymbolAddress((void**)&wol, g_wol);

    cudaFuncSetAttribute(bfgemm3_kernel,
                         cudaFuncAttributeMaxDynamicSharedMemorySize, SMEM_BYTES);

    const int M = B_*L_;   // 4096
    const float qscale = 0.08838834764831845f;   // 128^-0.5

    // 0: split hidden -> bf16 hi/lo
    split_kernel<<<(M*D_)/1024, 256>>>(hidden, hh, hl, M*D_);
    // 1: split+transpose Wq
    splitT_kernel<<<dim3((H_*HD_)/32, D_/32, 1), 256>>>(Wq, wqh, wql, Wq, wqh, wql, D_, H_*HD_);
    // 2: split+transpose Wk, Wv
    splitT_kernel<<<dim3(HD_/32, D_/32, 2), 256>>>(Wk, wkh, wkl, Wv, wvh, wvl, D_, HD_);
    // 3: fused Q+K+V projections  (profiled slot)
    bfgemm3_kernel<<<dim3(20, M/128), 256, SMEM_BYTES>>>(M, D_, 16, 2,
        hh, hl, wqh, wql, q, H_*HD_, wkh, wkl, k, wvh, wvl, v);
    // 4: split+transpose Wo
    splitT_kernel<<<dim3(D_/32, (H_*HD_)/32, 1), 256>>>(Wo, woh, wol, Wo, woh, wol, H_*HD_, D_);
    // 5,6: RoPE
    rope_kernel<<<(B_*L_*HALF_ + 255)/256, 256>>>(k, fcos, fsin, 1);
    rope_kernel<<<(B_*L_*H_*HALF_ + 255)/256, 256>>>(q, fcos, fsin, H_);
    // 7,8: hedgehog
    hedgehog_kernel<<<dim3(L_/16, H_, B_), 256>>>(k, fmk, kf, 1, 1.0f);
    hedgehog_kernel<<<dim3(L_/16, H_, B_), 256>>>(q, fmq, qf, H_, qscale);
    // 9: per-chunk kv states
    kv2_kernel<<<dim3(NCH_, 2, B_*H_), 256>>>(kf, v, kv);
    // 10: exclusive cumsum
    cumsum_kernel<<<dim3(128, B_*H_), 256>>>(kv);
    // 11: inter + intra attention
    attn_kernel<<<dim3(NCH_, H_, B_), 256>>>(qf, kf, v, kv, o);
    // 12: split o
    split_kernel<<<(M*H_*HD_)/1024, 256>>>(o, oh, ol, M*H_*HD_);
    // 13: output projection
    bfgemm3_kernel<<<dim3(16, M/128), 256, SMEM_BYTES>>>(M, H_*HD_, 16, 0,
        oh, ol, woh, wol, out, D_, woh, wol, out, woh, wol, out);
}

// round 8
// speedup vs baseline: 1.3184x; 1.1520x over previous
#include <cuda_runtime.h>
#include <cuda_fp16.h>
#include <math.h>
#include <stdint.h>

// Problem constants
#define B_ 2
#define L_ 2048
#define D_ 2048
#define H_ 8
#define HD_ 256
#define FD_ 64
#define FEAT_ 128          // 2*FD
#define CHUNK_ 64
#define NCH_ (L_/CHUNK_)   // 32
#define HALF_ (HD_/2)      // 128

// ---------------- scratch (device globals; no allocation allowed) ----------
__device__ float g_q [B_*L_*H_*HD_];
__device__ float g_k [B_*L_*HD_];
__device__ float g_v [B_*L_*HD_];
__device__ float g_qf[B_*H_*L_*FEAT_];
__device__ float g_kf[B_*H_*L_*FEAT_];
__device__ float g_kv[B_*H_*NCH_*FEAT_*HD_];
__device__ float g_o [B_*L_*H_*HD_];

// fp16 split operands: activations hi/lo, weights hi only
__device__ __half g_hh[B_*L_*D_], g_hl[B_*L_*D_];          // hidden hi/lo
__device__ __half g_oh[B_*L_*H_*HD_], g_ol[B_*L_*H_*HD_];  // o hi/lo
__device__ __half g_wqh[D_*H_*HD_];                         // WqT [N,K] hi
__device__ __half g_wkh[HD_*D_];                            // WkT hi
__device__ __half g_wvh[HD_*D_];                            // WvT hi
__device__ __half g_woh[D_*H_*HD_];                         // WoT hi

// ---------------- helpers ---------------------------------------------------
__device__ __forceinline__ void mma_f16(float* d,
                                        const uint32_t* a,
                                        const uint32_t* b) {
    asm volatile(
        "mma.sync.aligned.m16n8k16.row.col.f32.f16.f16.f32 "
        "{%0,%1,%2,%3}, {%4,%5,%6,%7}, {%8,%9}, {%0,%1,%2,%3};\n"
        : "+f"(d[0]), "+f"(d[1]), "+f"(d[2]), "+f"(d[3])
        : "r"(a[0]), "r"(a[1]), "r"(a[2]), "r"(a[3]),
          "r"(b[0]), "r"(b[1]));
}
__device__ __forceinline__ void cp16s(uint32_t saddr, const void* g) {
    asm volatile("cp.async.ca.shared.global [%0], [%1], 16;\n"
                 :: "r"(saddr), "l"(g));
}
__device__ __forceinline__ void cp_commit() {
    asm volatile("cp.async.commit_group;\n");
}
__device__ __forceinline__ void ldsm4(uint32_t* r, uint32_t saddr) {
    asm volatile("ldmatrix.sync.aligned.m8n8.x4.shared.b16 {%0,%1,%2,%3}, [%4];\n"
                 : "=r"(r[0]), "=r"(r[1]), "=r"(r[2]), "=r"(r[3]) : "r"(saddr));
}

// ---------------- split kernels --------------------------------------------
// fp32 -> fp16 hi + fp16 lo (lo = rn16(x - float(hi)))
__global__ __launch_bounds__(256)
void split_kernel(const float* __restrict__ x,
                  __half* __restrict__ hi,
                  __half* __restrict__ lo, int n) {
    int i = (blockIdx.x*256 + threadIdx.x) * 4;
    if (i >= n) return;
    float4 v = *(const float4*)(x + i);
    __half2 h0 = __floats2half2_rn(v.x, v.y);
    __half2 h1 = __floats2half2_rn(v.z, v.w);
    __half2 l0 = __floats2half2_rn(v.x - __half2float(__low2half(h0)),
                                   v.y - __half2float(__high2half(h0)));
    __half2 l1 = __floats2half2_rn(v.z - __half2float(__low2half(h1)),
                                   v.w - __half2float(__high2half(h1)));
    *(__half2*)(hi + i)     = h0;
    *(__half2*)(hi + i + 2) = h1;
    *(__half2*)(lo + i)     = l0;
    *(__half2*)(lo + i + 2) = l1;
}

// W [K,N] fp32 -> WT hi [N,K] fp16 (z batches two matrices)
__global__ __launch_bounds__(256)
void splitT_kernel(const float* __restrict__ W0, __half* th0,
                   const float* __restrict__ W1, __half* th1,
                   int K, int N) {
    const float* W = blockIdx.z ? W1 : W0;
    __half* th = blockIdx.z ? th1 : th0;
    __shared__ float tile[32][33];
    int n0 = blockIdx.x*32, k0 = blockIdx.y*32;
    int tx = threadIdx.x & 31, ty = threadIdx.x >> 5;
    #pragma unroll
    for (int r = 0; r < 32; r += 8)
        tile[ty + r][tx] = W[(size_t)(k0 + ty + r)*N + n0 + tx];
    __syncthreads();
    #pragma unroll
    for (int r = 0; r < 32; r += 8) {
        float v = tile[tx][ty + r];
        th[(size_t)(n0 + ty + r)*K + k0 + tx] = __float2half_rn(v);
    }
}

// ============================================================================
// hgemm: fp16 2-term GEMM. C = A @ B; A = (Ah + Al) fp16 [M,K];
// B = Bh fp16 transposed [N,K] (single term — fp16's 10 mantissa bits keep
// the weight-rounding error ~2^-11 rel, under the 1e-3 gate with margin).
// 3-stage cp.async pipeline + ldmatrix; block 128x128x16; 8 warps (2x4).
// Per k16 slab: 2 MMAs per (mt,nt) -> 32 MMAs, 10 ldmatrix.x4.
// grid.x: [0,nq) -> Q, [nq,nq+nk) -> K, rest -> V.
// ============================================================================
#define LDWW 12            // words per row (8 data + 4 pad)
#define SECW (128*LDWW)    // 1536 words per section
#define STW  (3*SECW)      // 4608 words per stage (Ah, Al, Bh)
#define SMEM_BYTES (3*STW*4)   // 55296

__global__ __launch_bounds__(256, 2)
void hgemm_kernel(int M, int K, int nq, int nk,
                  const __half* __restrict__ Ah,
                  const __half* __restrict__ Al,
                  const __half* __restrict__ qBh, float* __restrict__ qC, int qN,
                  const __half* __restrict__ kBh, float* __restrict__ kC,
                  const __half* __restrict__ vBh, float* __restrict__ vC) {
    extern __shared__ uint32_t smem[];
    const uint32_t smem_u32 = (uint32_t)__cvta_generic_to_shared(smem);

    const int cx = blockIdx.x;
    const __half* Bh;
    float* C;
    int N, ccol;
    if (cx < nq)           { Bh = qBh; C = qC; N = qN;  ccol = cx; }
    else if (cx < nq + nk) { Bh = kBh; C = kC; N = 256; ccol = cx - nq; }
    else                   { Bh = vBh; C = vC; N = 256; ccol = cx - nq - nk; }

    const int tid = threadIdx.x, lane = tid & 31, warp = tid >> 5;
    const int warpM = warp & 1, warpN = warp >> 1;
    const int cRow = blockIdx.y;

    // copy mapping: each thread 1x16B per section
    const int row = tid >> 1, half = tid & 1;
    const __half* aH = Ah + (size_t)(cRow*128 + row)*K + half*8;
    const __half* aL = Al + (size_t)(cRow*128 + row)*K + half*8;
    const __half* bH = Bh + (size_t)(ccol*128 + row)*K + half*8;
    const uint32_t dstw = row*LDWW + half*4;

    // ldmatrix per-lane offsets (words)
    const int l7 = lane & 7;
    const uint32_t aoffw = (uint32_t)((warpM*64 + l7 + ((lane>>3)&1)*8)*LDWW + (lane>>4)*4);
    uint32_t boffw[2];
    #pragma unroll
    for (int p = 0; p < 2; p++)
        boffw[p] = (uint32_t)((warpN*32 + p*16 + l7 + ((lane>>4)&1)*8)*LDWW + ((lane>>3)&1)*4);

    float acc[4][4][4];
    #pragma unroll
    for (int mt = 0; mt < 4; mt++)
        #pragma unroll
        for (int nt = 0; nt < 4; nt++)
            #pragma unroll
            for (int i = 0; i < 4; i++) acc[mt][nt][i] = 0.f;

    const int KT = K >> 4;

    // prologue: stages 0 and 1
    #pragma unroll
    for (int s = 0; s < 2; s++) {
        const int ko = s*16;
        const uint32_t sb = smem_u32 + (s*STW)*4;
        cp16s(sb + (0*SECW + dstw)*4, aH + ko);
        cp16s(sb + (1*SECW + dstw)*4, aL + ko);
        cp16s(sb + (2*SECW + dstw)*4, bH + ko);
        cp_commit();
    }

    int sc = 0;
    for (int kt = 0; kt < KT; kt++) {
        if (kt < KT - 1) { asm volatile("cp.async.wait_group 1;\n"); }
        else             { asm volatile("cp.async.wait_group 0;\n"); }
        __syncthreads();

        if (kt + 2 < KT) {
            const int sl = (sc + 2 >= 3) ? sc - 1 : sc + 2;
            const int ko = (kt + 2)*16;
            const uint32_t sb = smem_u32 + (sl*STW)*4;
            cp16s(sb + (0*SECW + dstw)*4, aH + ko);
            cp16s(sb + (1*SECW + dstw)*4, aL + ko);
            cp16s(sb + (2*SECW + dstw)*4, bH + ko);
            cp_commit();
        }

        const uint32_t sb = smem_u32 + (sc*STW)*4;

        uint32_t bhf[2][4];
        #pragma unroll
        for (int p = 0; p < 2; p++)
            ldsm4(bhf[p], sb + (2*SECW + boffw[p])*4);

        #pragma unroll
        for (int mt = 0; mt < 4; mt++) {
            uint32_t ahf[4], alf[4];
            const uint32_t ao = aoffw + mt*16*LDWW;
            ldsm4(ahf, sb + (0*SECW + ao)*4);
            ldsm4(alf, sb + (1*SECW + ao)*4);
            #pragma unroll
            for (int nt = 0; nt < 4; nt++) {
                const uint32_t* bp = &bhf[nt >> 1][(nt & 1)*2];
                mma_f16(acc[mt][nt], ahf, bp);
                mma_f16(acc[mt][nt], alf, bp);
            }
        }
        sc = (sc + 1 == 3) ? 0 : sc + 1;
    }

    // epilogue
    const int g = lane >> 2, t4 = lane & 3;
    float* Cb = C + (size_t)cRow*128*N + ccol*128;
    #pragma unroll
    for (int mt = 0; mt < 4; mt++) {
        const int r0 = warpM*64 + mt*16 + g;
        #pragma unroll
        for (int nt = 0; nt < 4; nt++) {
            const int c = warpN*32 + nt*8 + t4*2;
            *(float2*)&Cb[(size_t)r0 * N + c]       = make_float2(acc[mt][nt][0], acc[mt][nt][1]);
            *(float2*)&Cb[(size_t)(r0 + 8) * N + c] = make_float2(acc[mt][nt][2], acc[mt][nt][3]);
        }
    }
}

// ---------------- RoPE (in place) -----------------------------------------
__global__ void rope_kernel(float* __restrict__ x,
                            const float* __restrict__ cs,
                            const float* __restrict__ sn,
                            int heads) {
    int idx = blockIdx.x*blockDim.x + threadIdx.x;
    int total = B_*L_*heads*HALF_;
    if (idx >= total) return;
    int j = idx % HALF_;
    int h = (idx / HALF_) % heads;
    int l = (idx / (HALF_*heads)) % L_;
    int b =  idx / (HALF_*heads*L_);
    float c = cs[l*HALF_ + j];
    float s = sn[l*HALF_ + j];
    float* row = x + ((size_t)(b*L_ + l)*heads + h)*HD_;
    float x1 = row[j], x2 = row[j + HALF_];
    row[j]        = x1*c - x2*s;
    row[j + HALF_] = x1*s + x2*c;
}

// ---------------- Hedgehog feature map ------------------------------------
__global__ __launch_bounds__(256)
void hedgehog_kernel(const float* __restrict__ x,
                     const float* __restrict__ fm,
                     float* __restrict__ outf,
                     int xh, float scale) {
    __shared__ float xs[16][HD_];
    __shared__ float ps[16][FD_];
    __shared__ float ms[16], zs[16];

    int h = blockIdx.y, b = blockIdx.z;
    int l0 = blockIdx.x * 16;
    int t = threadIdx.x;
    int srcH = (xh == 1) ? 0 : h;

    for (int e = t; e < 16*HD_; e += 256) {
        int r = e / HD_, d = e % HD_;
        xs[r][d] = x[((size_t)(b*L_ + l0 + r)*xh + srcH)*HD_ + d];
    }
    __syncthreads();

    int r  = t / 16;
    int fb = (t % 16) * 4;
    float a0=0.f, a1=0.f, a2=0.f, a3=0.f;
    const float* fmh = fm + (size_t)h*HD_*FD_;
    #pragma unroll 4
    for (int d = 0; d < HD_; d++) {
        float xv = xs[r][d];
        float4 w = *(const float4*)&fmh[d*FD_ + fb];
        a0 += xv*w.x; a1 += xv*w.y; a2 += xv*w.z; a3 += xv*w.w;
    }
    ps[r][fb+0]=a0; ps[r][fb+1]=a1; ps[r][fb+2]=a2; ps[r][fb+3]=a3;
    __syncthreads();

    if (t < 16) {
        float m = 0.f;
        for (int f = 0; f < FD_; f++) m = fmaxf(m, fabsf(ps[t][f]));
        float z = 0.f;
        for (int f = 0; f < FD_; f++)
            z += __expf(ps[t][f] - m) + __expf(-ps[t][f] - m);
        ms[t] = m; zs[t] = z;
    }
    __syncthreads();

    for (int e = t; e < 16*FEAT_; e += 256) {
        int rr = e / FEAT_, f = e % FEAT_;
        float p = (f < FD_) ? ps[rr][f] : -ps[rr][f - FD_];
        float val = __expf(p - ms[rr]) / zs[rr] * scale;
        outf[((size_t)(b*H_ + h)*L_ + l0 + rr)*FEAT_ + f] = val;
    }
}

// ---------------- per-chunk kv state (register-tiled) ----------------------
__global__ __launch_bounds__(256)
void kv2_kernel(const float* __restrict__ kf, const float* __restrict__ v,
                float* __restrict__ kv) {
    __shared__ float ks[32][FEAT_];
    __shared__ float vs[32][128];
    int n  = blockIdx.x;
    int dh = blockIdx.y;
    int bh = blockIdx.z;
    int b  = bh / H_;
    int t  = threadIdx.x;
    int tf = t >> 4;
    int td = t & 15;

    const float* kfp = kf + ((size_t)bh*L_ + n*CHUNK_)*FEAT_;
    const float* vp  = v  + ((size_t)b*L_  + n*CHUNK_)*HD_ + dh*128;

    float acc[8][8];
    #pragma unroll
    for (int i = 0; i < 8; i++)
        #pragma unroll
        for (int j = 0; j < 8; j++) acc[i][j] = 0.f;

    for (int cc = 0; cc < 2; cc++) {
        for (int e = t; e < 32*FEAT_; e += 256)
            ks[e >> 7][e & 127] = kfp[cc*32*FEAT_ + e];
        for (int e = t; e < 32*128; e += 256) {
            int r = e >> 7, c = e & 127;
            vs[r][c] = vp[(size_t)(cc*32 + r)*HD_ + c];
        }
        __syncthreads();

        #pragma unroll 4
        for (int c = 0; c < 32; c++) {
            float4 ka = *(const float4*)&ks[c][tf*8];
            float4 kb = *(const float4*)&ks[c][tf*8 + 4];
            float4 va = *(const float4*)&vs[c][td*4];
            float4 vb = *(const float4*)&vs[c][64 + td*4];
            float kk[8] = {ka.x,ka.y,ka.z,ka.w,kb.x,kb.y,kb.z,kb.w};
            float vv[8] = {va.x,va.y,va.z,va.w,vb.x,vb.y,vb.z,vb.w};
            #pragma unroll
            for (int i = 0; i < 8; i++)
                #pragma unroll
                for (int j = 0; j < 8; j++)
                    acc[i][j] += kk[i]*vv[j];
        }
        __syncthreads();
    }

    float* out = kv + ((size_t)(bh*NCH_ + n)*FEAT_)*HD_ + dh*128;
    #pragma unroll
    for (int i = 0; i < 8; i++) {
        size_t ro = (size_t)(tf*8 + i)*HD_;
        *(float4*)&out[ro + td*4]      = make_float4(acc[i][0], acc[i][1], acc[i][2], acc[i][3]);
        *(float4*)&out[ro + 64 + td*4] = make_float4(acc[i][4], acc[i][5], acc[i][6], acc[i][7]);
    }
}

// ---------------- exclusive cumsum over chunk axis (in place) -------------
__global__ void cumsum_kernel(float* __restrict__ kv) {
    int bh = blockIdx.y;
    int e  = blockIdx.x*256 + threadIdx.x;
    float* base = kv + (size_t)bh*NCH_*FEAT_*HD_ + e;
    float run = 0.f;
    for (int n = 0; n < NCH_; n++) {
        float tmp = base[(size_t)n*FEAT_*HD_];
        base[(size_t)n*FEAT_*HD_] = run;
        run += tmp;
    }
}

// ---------------- inter + intra chunk attention ---------------------------
__global__ __launch_bounds__(256)
void attn_kernel(const float* __restrict__ qf, const float* __restrict__ kf,
                 const float* __restrict__ v,  const float* __restrict__ kv,
                 float* __restrict__ o) {
    __shared__ float qs[CHUNK_][FEAT_];
    __shared__ float ss[CHUNK_][CHUNK_];
    int n = blockIdx.x, h = blockIdx.y, b = blockIdx.z;
    int bh = b*H_ + h;
    int t = threadIdx.x;
    int j = t;

    const float* qp = qf + ((size_t)bh*L_ + n*CHUNK_)*FEAT_;
    for (int e = t; e < CHUNK_*FEAT_; e += 256) qs[e/FEAT_][e%FEAT_] = qp[e];
    __syncthreads();

    float acc[CHUNK_];
    #pragma unroll
    for (int i = 0; i < CHUNK_; i++) acc[i] = 0.f;

    const float* kvp = kv + ((size_t)(bh*NCH_ + n)*FEAT_)*HD_;
    for (int f = 0; f < FEAT_; f += 4) {
        float k0 = kvp[(size_t)(f+0)*HD_ + j];
        float k1 = kvp[(size_t)(f+1)*HD_ + j];
        float k2 = kvp[(size_t)(f+2)*HD_ + j];
        float k3 = kvp[(size_t)(f+3)*HD_ + j];
        #pragma unroll
        for (int i = 0; i < CHUNK_; i++) {
            float4 qv = *(const float4*)&qs[i][f];
            acc[i] += qv.x*k0 + qv.y*k1 + qv.z*k2 + qv.w*k3;
        }
    }

    {
        const float* kp = kf + ((size_t)bh*L_ + n*CHUNK_)*FEAT_;
        int i   = t / 4;
        int jp0 = (t % 4) * 16;
        for (int jj = 0; jj < 16; jj++) {
            int jp = jp0 + jj;
            float sum = 0.f;
            if (jp <= i) {
                const float* krow = kp + (size_t)jp*FEAT_;
                #pragma unroll 8
                for (int f = 0; f < FEAT_; f += 4) {
                    float4 qv = *(const float4*)&qs[i][f];
                    float4 kr = *(const float4*)&krow[f];
                    sum += qv.x*kr.x + qv.y*kr.y + qv.z*kr.z + qv.w*kr.w;
                }
            }
            ss[i][jp] = sum;
        }
    }
    __syncthreads();

    const float* vp = v + ((size_t)b*L_ + n*CHUNK_)*HD_;
    for (int jp = 0; jp < CHUNK_; jp += 4) {
        float v0 = vp[(size_t)(jp+0)*HD_ + j];
        float v1 = vp[(size_t)(jp+1)*HD_ + j];
        float v2 = vp[(size_t)(jp+2)*HD_ + j];
        float v3 = vp[(size_t)(jp+3)*HD_ + j];
        #pragma unroll
        for (int i = 0; i < CHUNK_; i++) {
            float4 sv = *(const float4*)&ss[i][jp];
            acc[i] += sv.x*v0 + sv.y*v1 + sv.z*v2 + sv.w*v3;
        }
    }

    float* op = o + ((size_t)(b*L_ + n*CHUNK_))*(H_*HD_) + h*HD_ + j;
    #pragma unroll
    for (int i = 0; i < CHUNK_; i++) op[(size_t)i*(H_*HD_)] = acc[i];
}

// ---------------- launch ---------------------------------------------------
extern "C" void kernel_launch(void* const* d_in, const int* in_sizes, int n_in,
                              void* d_out, int out_size) {
    const float* hidden = (const float*)d_in[0];
    const float* fcos   = (const float*)d_in[1];
    const float* fsin   = (const float*)d_in[2];
    // d_in[3] = mask (unused)
    const float* Wq     = (const float*)d_in[4];
    const float* Wk     = (const float*)d_in[5];
    const float* Wv     = (const float*)d_in[6];
    const float* Wo     = (const float*)d_in[7];
    const float* fmq    = (const float*)d_in[8];
    const float* fmk    = (const float*)d_in[9];
    float* out          = (float*)d_out;

    float *q, *k, *v, *qf, *kf, *kv, *o;
    cudaGetSymbolAddress((void**)&q,  g_q);
    cudaGetSymbolAddress((void**)&k,  g_k);
    cudaGetSymbolAddress((void**)&v,  g_v);
    cudaGetSymbolAddress((void**)&qf, g_qf);
    cudaGetSymbolAddress((void**)&kf, g_kf);
    cudaGetSymbolAddress((void**)&kv, g_kv);
    cudaGetSymbolAddress((void**)&o,  g_o);

    __half *hh,*hl,*oh,*ol,*wqh,*wkh,*wvh,*woh;
    cudaGetSymbolAddress((void**)&hh,  g_hh);  cudaGetSymbolAddress((void**)&hl,  g_hl);
    cudaGetSymbolAddress((void**)&oh,  g_oh);  cudaGetSymbolAddress((void**)&ol,  g_ol);
    cudaGetSymbolAddress((void**)&wqh, g_wqh);
    cudaGetSymbolAddress((void**)&wkh, g_wkh);
    cudaGetSymbolAddress((void**)&wvh, g_wvh);
    cudaGetSymbolAddress((void**)&woh, g_woh);

    cudaFuncSetAttribute(hgemm_kernel,
                         cudaFuncAttributeMaxDynamicSharedMemorySize, SMEM_BYTES);

    const int M = B_*L_;   // 4096
    const float qscale = 0.08838834764831845f;   // 128^-0.5

    // 0: split hidden -> fp16 hi/lo
    split_kernel<<<(M*D_)/1024, 256>>>(hidden, hh, hl, M*D_);
    // 1: transpose+convert Wq
    splitT_kernel<<<dim3((H_*HD_)/32, D_/32, 1), 256>>>(Wq, wqh, Wq, wqh, D_, H_*HD_);
    // 2: transpose+convert Wk, Wv
    splitT_kernel<<<dim3(HD_/32, D_/32, 2), 256>>>(Wk, wkh, Wv, wvh, D_, HD_);
    // 3: fused Q+K+V projections (profiled slot)
    hgemm_kernel<<<dim3(20, M/128), 256, SMEM_BYTES>>>(M, D_, 16, 2,
        hh, hl, wqh, q, H_*HD_, wkh, k, wvh, v);
    // 4: transpose+convert Wo
    splitT_kernel<<<dim3(D_/32, (H_*HD_)/32, 1), 256>>>(Wo, woh, Wo, woh, H_*HD_, D_);
    // 5,6: RoPE
    rope_kernel<<<(B_*L_*HALF_ + 255)/256, 256>>>(k, fcos, fsin, 1);
    rope_kernel<<<(B_*L_*H_*HALF_ + 255)/256, 256>>>(q, fcos, fsin, H_);
    // 7,8: hedgehog
    hedgehog_kernel<<<dim3(L_/16, H_, B_), 256>>>(k, fmk, kf, 1, 1.0f);
    hedgehog_kernel<<<dim3(L_/16, H_, B_), 256>>>(q, fmq, qf, H_, qscale);
    // 9: per-chunk kv states
    kv2_kernel<<<dim3(NCH_, 2, B_*H_), 256>>>(kf, v, kv);
    // 10: exclusive cumsum
    cumsum_kernel<<<dim3(128, B_*H_), 256>>>(kv);
    // 11: inter + intra attention
    attn_kernel<<<dim3(NCH_, H_, B_), 256>>>(qf, kf, v, kv, o);
    // 12: split o
    split_kernel<<<(M*H_*HD_)/1024, 256>>>(o, oh, ol, M*H_*HD_);
    // 13: output projection
    hgemm_kernel<<<dim3(16, M/128), 256, SMEM_BYTES>>>(M, H_*HD_, 16, 0,
        oh, ol, woh, out, D_, woh, out, woh, out);
}